// round 16
// baseline (speedup 1.0000x reference)
#include <cuda_runtime.h>
#include <cuda_fp16.h>
#include <math.h>
#include <stdint.h>

#define NCB   8
#define MEMB  1024
#define DEMB  128
#define HLAT  64
#define BATCH 256
#define LPER  (BATCH*HLAT)              /* 16384 per codebook */
#define ZQ_ELEMS (BATCH*NCB*DEMB*HLAT)  /* 16777216 */
#define IDX_ELEMS (BATCH*NCB*HLAT)      /* 131072 */

// ---------------- device scratch ----------------
__device__ int   g_indices[NCB*LPER];
__device__ float g_esq[NCB*MEMB];
__device__ int   g_esqmaxb[NCB];
__device__ float g_xsq[NCB*LPER];
__device__ float g_part[2048];
__device__ float g_ent[NCB];
__device__ int   g_paircnt;
__device__ int2  g_pairlist[NCB*LPER];        // .x=(n<<14)|l, .y=i1|(i2<<16)
__device__ float g_xpp[(size_t)NCB*LPER*DEMB]; // packed x rows for pair entries
__device__ int   g_rcnt[NCB];
__device__ int   g_rlist[NCB*LPER];
__device__ float g_xpr[(size_t)NCB*LPER*DEMB];
__device__ unsigned long long g_fixkey[NCB*LPER];
// pre-swizzled fp16 embedding tiles (e*256): [n][mchunk 16][row 64][k 128]
__device__ __half g_bh[NCB*MEMB*DEMB];

// ---------------- PTX helpers ----------------
__device__ __forceinline__ uint32_t smem_u32(const void* p) {
    uint32_t a;
    asm("{ .reg .u64 t; cvta.to.shared.u64 t, %1; cvt.u32.u64 %0, t; }" : "=r"(a) : "l"(p));
    return a;
}
__device__ __forceinline__ void ldsm4(uint32_t* r, uint32_t addr) {
    asm volatile("ldmatrix.sync.aligned.m8n8.x4.shared.b16 {%0,%1,%2,%3}, [%4];"
        : "=r"(r[0]), "=r"(r[1]), "=r"(r[2]), "=r"(r[3]) : "r"(addr));
}
__device__ __forceinline__ void mma_f16(float* c, const uint32_t* a, const uint32_t* b) {
    asm volatile("mma.sync.aligned.m16n8k16.row.col.f32.f16.f16.f32 "
        "{%0,%1,%2,%3}, {%4,%5,%6,%7}, {%8,%9}, {%0,%1,%2,%3};"
        : "+f"(c[0]), "+f"(c[1]), "+f"(c[2]), "+f"(c[3])
        : "r"(a[0]), "r"(a[1]), "r"(a[2]), "r"(a[3]), "r"(b[0]), "r"(b[1]));
}
__device__ __forceinline__ void cp16(uint32_t dst, const void* src) {
    asm volatile("cp.async.cg.shared.global [%0], [%1], 16;" :: "r"(dst), "l"(src) : "memory");
}
#define CP_COMMIT() asm volatile("cp.async.commit_group;" ::: "memory")
#define CP_WAIT(n)  asm volatile("cp.async.wait_group %0;" :: "n"(n) : "memory")

// merge two sorted float triples (7 FMNMX ops; keys positive, unique)
__device__ __forceinline__ void kmrg(float& a1, float& a2, float& a3,
                                     float b1, float b2, float b3) {
    float M  = fmaxf(a1, b1);
    float m2 = fminf(a2, b2);
    float r1 = fminf(a1, b1);
    float r2 = fminf(M, m2);
    float r3 = fminf(fminf(a3, b3), fmaxf(m2, M));
    a1 = r1; a2 = r2; a3 = r3;
}

// ---------------- e_sq (exact sequential) + per-n max + counter reset ----------------
__global__ void esq_kernel(const float* __restrict__ emb) {
    int t = blockIdx.x * blockDim.x + threadIdx.x;
    if (t == 0) g_paircnt = 0;
    if (t < NCB) g_rcnt[t] = 0;
    if (t >= NCB*MEMB) return;
    const float* row = emb + (size_t)t * DEMB;
    float acc = 0.f;
    #pragma unroll 8
    for (int d = 0; d < DEMB; d++) {
        float v = row[d];
        acc = __fadd_rn(acc, __fmul_rn(v, v));
    }
    g_esq[t] = acc;
    atomicMax(&g_esqmaxb[t >> 10], __float_as_int(acc));
}

// ---------------- x_sq (exact sequential) ----------------
__global__ void __launch_bounds__(256)
xsq_kernel(const float* __restrict__ x) {
    __shared__ float tile[8192];
    const int n = blockIdx.x & 7, b = blockIdx.x >> 3, tid = threadIdx.x;
    const size_t base = (size_t)b*65536 + (size_t)n*8192;
    for (int i = tid; i < 8192; i += 256) tile[i] = x[base + i];
    __syncthreads();
    if (tid < 64) {
        float acc = 0.f;
        #pragma unroll 8
        for (int d = 0; d < DEMB; d++) {
            float v = tile[d*64 + tid];
            acc = __fadd_rn(acc, __fmul_rn(v, v));
        }
        g_xsq[n*LPER + b*HLAT + tid] = acc;
    }
}

// ---------------- embedding -> swizzled fp16 (e*256) tiles, 64-code chunks ----------------
__global__ void bprep_kernel(const float* __restrict__ emb) {
    int u = blockIdx.x * blockDim.x + threadIdx.x;
    if (u >= NCB*MEMB*DEMB) return;
    float v = emb[u] * 256.0f;
    int d = u & 127, m = (u >> 7) & 1023, n = u >> 17;
    int row = m & 63, mc = m >> 6;
    int elem = ((n*16 + mc)*64 + row)*128 + (((d >> 3) ^ (row & 7)) << 3) + (d & 7);
    g_bh[elem] = __float2half_rn(v);
}

// ---------------- pass 1: fp16 1-MMA argmin, A frags in regs, float-key top-3 ----------------
// CTA = (n, batch row). 8 warps = 2(l) x 4(m); warp tile 32x16.
// Epilogue: FMNMX tournament with chunk-min skip (FMA pipe, not ALU).
__global__ void __launch_bounds__(256, 2)
argmin_mma(const float* __restrict__ x) {
    extern __shared__ char sm[];
    const uint32_t sb = smem_u32(sm);
    // B buffers: buf0 @0 (16KB), buf1 @16384 (16KB)
    __half* Ast = (__half*)(sm + 32768);      // A staging 16KB
    float* esq1_s = (float*)(sm + 49152);     // 4KB  (esq + 1.0)
    float* sk1 = (float*)(sm + 53248);        // 1KB
    float* sk2 = (float*)(sm + 54272);        // 1KB
    float* sk3 = (float*)(sm + 55296);        // 1KB

    const int n  = blockIdx.x >> 8;
    const int lt = blockIdx.x & 255;          // batch row b
    const int l0 = lt * 64;
    const int tid  = threadIdx.x;
    const int lane = tid & 31;
    const int w    = tid >> 5;
    const int wl   = w & 1;     // l half (32 rows)
    const int wm   = w >> 1;    // m quarter (16 cols of the 64-chunk)

    // prefetch B chunk 0 -> buf0
    {
        const char* src = (const char*)(g_bh + ((size_t)(n*16 + 0) << 13));
        #pragma unroll
        for (int i = 0; i < 4; i++)
            cp16(sb + (tid + i*256)*16, src + (tid + i*256)*16);
        CP_COMMIT();
    }

    // stage esq+1
    for (int i = tid; i < 1024; i += 256) esq1_s[i] = g_esq[n*1024 + i] + 1.0f;

    // stage A tile fp16 (swizzled): rows j = h (0..63), cols d
    for (int idx = tid; idx < 8192; idx += 256) {
        int d = idx >> 6, j = idx & 63;
        float v = x[(size_t)lt*65536 + (size_t)n*8192 + d*64 + j];
        int elem = j*128 + (((d >> 3) ^ (j & 7)) << 3) + (d & 7);
        Ast[elem] = __float2half_rn(v);
    }
    __syncthreads();   // A staging visible

    // per-lane addressing
    const int q  = lane >> 3;
    const int r8 = lane & 7;
    const int cqA = q >> 1;
    const int cqB = q & 1;

    // hoist A fragments into registers: ah[ks*2+t2][4]
    uint32_t ah[16][4];
    {
        #pragma unroll
        for (int t2 = 0; t2 < 2; t2++) {
            int rowA = wl*32 + t2*16 + r8 + (q & 1)*8;
            uint32_t aBase = sb + 32768u + (uint32_t)rowA*256u;
            int a7 = rowA & 7;
            #pragma unroll
            for (int ks = 0; ks < 8; ks++) {
                uint32_t off = (uint32_t)(((ks*2 + cqA) ^ a7) << 4);
                ldsm4(ah[ks*2 + t2], aBase + off);
            }
        }
    }

    uint32_t bBase; int b7;
    {
        int rowB = wm*16 + r8 + (q >> 1)*8;
        bBase = sb + (uint32_t)rowB*256u; b7 = rowB & 7;
    }

    // float-key top-3 per slot: slots = (t2, row-half)
    float K1[4], K2[4], K3[4];
    #pragma unroll
    for (int s = 0; s < 4; s++) { K1[s] = 3.0e38f; K2[s] = 3.0e38f; K3[s] = 3.0e38f; }

    const int col2 = (lane & 3) * 2;

#define LADF(s, k) { \
    float b_ = fmaxf(K1[s], (k)); K1[s] = fminf(K1[s], (k)); \
    float c_ = fmaxf(K2[s], b_);  K2[s] = fminf(K2[s], b_); \
    K3[s] = fminf(K3[s], c_); }

    for (int mc = 0; mc < 16; mc++) {
        if (mc < 15) {
            const char* src = (const char*)(g_bh + ((size_t)(n*16 + mc + 1) << 13));
            uint32_t dbuf = sb + (uint32_t)(((mc + 1) & 1) * 16384);
            #pragma unroll
            for (int i = 0; i < 4; i++)
                cp16(dbuf + (tid + i*256)*16, src + (tid + i*256)*16);
            CP_COMMIT();
            CP_WAIT(1);
        } else {
            CP_WAIT(0);
        }
        __syncthreads();

        const uint32_t bufOff = (uint32_t)((mc & 1) * 16384);

        float acc[2][2][4];
        #pragma unroll
        for (int t2 = 0; t2 < 2; t2++)
            #pragma unroll
            for (int mt = 0; mt < 2; mt++)
                #pragma unroll
                for (int c = 0; c < 4; c++) acc[t2][mt][c] = 0.f;

        #pragma unroll
        for (int ks = 0; ks < 8; ks++) {
            uint32_t bh[4];
            {
                uint32_t off = (uint32_t)(((ks*2 + cqB) ^ b7) << 4) + bufOff;
                ldsm4(bh, bBase + off);
            }
            #pragma unroll
            for (int t2 = 0; t2 < 2; t2++) {
                mma_f16(acc[t2][0], ah[ks*2 + t2], &bh[0]);
                mma_f16(acc[t2][1], ah[ks*2 + t2], &bh[2]);
            }
        }

        // epilogue: t' = (esq+1) - acc/128 ; float key = bits&~1023 | m.
        // Per slot: 4 candidate keys; chunk-min tournament skips the ladder
        // unless the chunk can touch the current top-3 (rare).
        const int mbase = mc*64 + wm*16;
        {
            float e0a = esq1_s[mbase + col2];
            float e1a = esq1_s[mbase + col2 + 1];
            float e0b = esq1_s[mbase + 8 + col2];
            float e1b = esq1_s[mbase + 8 + col2 + 1];
            uint32_t mA = (uint32_t)(mbase + col2);
            uint32_t mB = (uint32_t)(mbase + 8 + col2);
            #pragma unroll
            for (int s = 0; s < 4; s++) {
                const int t2 = s >> 1;          // slot layout: s = t2*2 + half
                const int hf = s & 1;           // half selects acc pair (rows g / g+8)
                float ta = fmaf(acc[t2][0][hf*2+0], -0.0078125f, e0a);
                float tb = fmaf(acc[t2][0][hf*2+1], -0.0078125f, e1a);
                float tc = fmaf(acc[t2][1][hf*2+0], -0.0078125f, e0b);
                float td = fmaf(acc[t2][1][hf*2+1], -0.0078125f, e1b);
                float ka = __uint_as_float((__float_as_uint(ta) & 0xFFFFFC00u) | mA);
                float kb = __uint_as_float((__float_as_uint(tb) & 0xFFFFFC00u) | (mA + 1u));
                float kc = __uint_as_float((__float_as_uint(tc) & 0xFFFFFC00u) | mB);
                float kd = __uint_as_float((__float_as_uint(td) & 0xFFFFFC00u) | (mB + 1u));
                float mn = fminf(fminf(ka, kb), fminf(kc, kd));
                if (mn < K3[s]) {               // rare after warm-up
                    LADF(s, ka); LADF(s, kb); LADF(s, kc); LADF(s, kd);
                }
            }
        }
        __syncthreads();   // all warps done reading this buffer before overwrite
    }
#undef LADF

    // quad reduce (lanes sharing lane>>2 hold the same rows)
    #pragma unroll
    for (int s = 0; s < 4; s++) {
        #pragma unroll
        for (int off = 1; off <= 2; off <<= 1) {
            float o1 = __shfl_xor_sync(0xffffffffu, K1[s], off);
            float o2 = __shfl_xor_sync(0xffffffffu, K2[s], off);
            float o3 = __shfl_xor_sync(0xffffffffu, K3[s], off);
            kmrg(K1[s], K2[s], K3[s], o1, o2, o3);
        }
    }
    if ((lane & 3) == 0) {
        const int g = lane >> 2;
        #pragma unroll
        for (int s = 0; s < 4; s++) {
            int row = wl*32 + (s & 1)*8 + g + (s >> 1)*16;
            sk1[wm*64 + row] = K1[s];
            sk2[wm*64 + row] = K2[s];
            sk3[wm*64 + row] = K3[s];
        }
    }
    __syncthreads();

    if (tid < 64) {
        float k1 = sk1[tid], k2 = sk2[tid], k3 = sk3[tid];
        #pragma unroll
        for (int qq = 1; qq < 4; qq++)
            kmrg(k1, k2, k3, sk1[qq*64 + tid], sk2[qq*64 + tid], sk3[qq*64 + tid]);

        uint32_t u1 = __float_as_uint(k1), u2 = __float_as_uint(k2), u3 = __float_as_uint(k3);
        int i1 = (int)(u1 & 1023u), i2 = (int)(u2 & 1023u);
        float b1f = __uint_as_float(u1 & 0xFFFFFC00u);
        float b2f = __uint_as_float(u2 & 0xFFFFFC00u);
        float b3f = __uint_as_float(u3 & 0xFFFFFC00u);

        int l = l0 + tid;
        int id = n*LPER + l;
        g_indices[id] = i1;
        float mar = 0.00390625f * sqrtf(g_xsq[id] * __int_as_float(g_esqmaxb[n])) + 5.0e-4f;
        if (b2f - b1f < mar) {
            if (b3f - b1f < mar) {
                g_fixkey[id] = 0xFFFFFFFFFFFFFFFFull;
                int p = atomicAdd(&g_rcnt[n], 1);
                g_rlist[n*LPER + p] = l;
            } else {
                int p = atomicAdd(&g_paircnt, 1);
                g_pairlist[p] = make_int2((n << 14) | l, i1 | (i2 << 16));
            }
        }
    }
}

// ---------------- pack pair x rows ----------------
__global__ void __launch_bounds__(128)
packP_kernel(const float* __restrict__ x) {
    const int cnt = g_paircnt;
    for (int u = blockIdx.x; u < cnt; u += gridDim.x) {
        int nl = g_pairlist[u].x;
        int n = nl >> 14, l = nl & 16383;
        int b = l >> 6, h = l & 63;
        g_xpp[(size_t)u*128 + threadIdx.x] =
            x[(size_t)b*65536 + (size_t)n*8192 + threadIdx.x*64 + h];
    }
}

// ---------------- pack rescan x rows ----------------
__global__ void __launch_bounds__(128)
packR_kernel(const float* __restrict__ x) {
    const int n = blockIdx.y;
    const int cnt = g_rcnt[n];
    for (int p = blockIdx.x; p < cnt; p += gridDim.x) {
        int l = g_rlist[n*LPER + p];
        int b = l >> 6, h = l & 63;
        g_xpr[((size_t)n*LPER + p)*128 + threadIdx.x] =
            x[(size_t)b*65536 + (size_t)n*8192 + threadIdx.x*64 + h];
    }
}

// ---------------- pass 2a: exact pairwise compare ----------------
__global__ void __launch_bounds__(256)
pairfix_kernel(const float* __restrict__ emb) {
    extern __shared__ float xsf[];            // [128 entries][stride 132]
    __shared__ float Dv[256];
    __shared__ int2  ent[128];
    const int tid = threadIdx.x;
    const int cnt = g_paircnt;

    for (int base = blockIdx.x*128; base < cnt; base += gridDim.x*128) {
        int nent = cnt - base; if (nent > 128) nent = 128;
        if (tid < nent) ent[tid] = g_pairlist[base + tid];
        __syncthreads();
        for (int i = tid; i < nent*32; i += 256) {
            int e = i >> 5, qv = (i & 31) * 4;
            float4 v = *(const float4*)&g_xpp[(size_t)(base + e)*128 + qv];
            float* dst = &xsf[e*132 + qv];
            dst[0] = v.x; dst[1] = v.y; dst[2] = v.z; dst[3] = v.w;
        }
        __syncthreads();
        if ((tid >> 1) < nent) {
            int e = tid >> 1, c = tid & 1;
            int nl = ent[e].x; int n = nl >> 14, l = nl & 16383;
            int m = c ? (ent[e].y >> 16) : (ent[e].y & 0xffff);
            const float4* er4 = (const float4*)(emb + ((size_t)n*1024 + m)*128);
            const float* xr = &xsf[e*132];
            float cc = 0.f;
            #pragma unroll 8
            for (int qq = 0; qq < 32; qq++) {
                float4 e4 = er4[qq];
                cc = fmaf(xr[qq*4+0], e4.x, cc);
                cc = fmaf(xr[qq*4+1], e4.y, cc);
                cc = fmaf(xr[qq*4+2], e4.z, cc);
                cc = fmaf(xr[qq*4+3], e4.w, cc);
            }
            Dv[tid] = __fsub_rn(__fadd_rn(g_esq[n*1024 + m], g_xsq[n*LPER + l]), 2.f*cc);
        }
        __syncthreads();
        if (tid < nent) {
            int m0 = ent[tid].y & 0xffff, m1 = ent[tid].y >> 16;
            float D0 = Dv[2*tid], D1 = Dv[2*tid + 1];
            int win;
            if (D0 < D1) win = m0;
            else if (D1 < D0) win = m1;
            else win = (m0 < m1) ? m0 : m1;
            int nl = ent[tid].x;
            g_indices[(nl >> 14)*LPER + (nl & 16383)] = win;
        }
        __syncthreads();
    }
}

// ---------------- pass 2b: full exact rescan, E staged in smem ----------------
__global__ void __launch_bounds__(128)
rescan_kernel(const float* __restrict__ emb) {
    extern __shared__ float fsm[];
    float* E     = fsm;                       // [128 codes][stride 132]
    float* xs    = fsm + 128*132;             // [8 rows][128]
    float* esq_c = xs + 1024;                 // [128]
    float* xsq_s = esq_c + 128;               // [8]
    unsigned long long* wred = (unsigned long long*)(xsq_s + 8);   // [4][8]

    const int n     = blockIdx.x >> 7;
    const int mc    = (blockIdx.x >> 4) & 7;
    const int slice = blockIdx.x & 15;
    const int tid   = threadIdx.x;
    const int wid   = tid >> 5, lane = tid & 31;

    const int cnt = g_rcnt[n];
    if (cnt == 0) return;

    const float* src = emb + ((size_t)n*1024 + mc*128)*128;
    for (int i = tid; i < 16384; i += 128) {
        int r = i >> 7, d = i & 127;
        E[r*132 + d] = src[i];
    }
    esq_c[tid] = g_esq[n*1024 + mc*128 + tid];
    __syncthreads();

    const unsigned code_m = (unsigned)(mc*128 + tid);

    for (int g0 = slice*8; g0 < cnt; g0 += 16*8) {
        #pragma unroll
        for (int r = 0; r < 8; r++) {
            int u = g0 + r;
            int uc = (u < cnt) ? u : (cnt - 1);
            xs[r*128 + tid] = g_xpr[((size_t)n*LPER + uc)*128 + tid];
        }
        if (tid < 8) {
            int u = g0 + tid;
            int uc = (u < cnt) ? u : (cnt - 1);
            xsq_s[tid] = g_xsq[n*LPER + g_rlist[n*LPER + uc]];
        }
        __syncthreads();

        float c[8];
        #pragma unroll
        for (int r = 0; r < 8; r++) c[r] = 0.f;
        const float4* er4 = (const float4*)&E[tid*132];
        #pragma unroll 8
        for (int qq = 0; qq < 32; qq++) {
            float4 e = er4[qq];
            #pragma unroll
            for (int r = 0; r < 8; r++) {
                float4 xr = *(const float4*)&xs[r*128 + qq*4];
                c[r] = fmaf(xr.x, e.x, c[r]);
                c[r] = fmaf(xr.y, e.y, c[r]);
                c[r] = fmaf(xr.z, e.z, c[r]);
                c[r] = fmaf(xr.w, e.w, c[r]);
            }
        }

        #pragma unroll
        for (int r = 0; r < 8; r++) {
            float D = __fsub_rn(__fadd_rn(esq_c[tid], xsq_s[r]), 2.f*c[r]);
            unsigned ud = __float_as_uint(D);
            ud = (ud & 0x80000000u) ? ~ud : (ud | 0x80000000u);
            unsigned long long key = ((unsigned long long)ud << 32) | code_m;
            #pragma unroll
            for (int o = 16; o; o >>= 1) {
                unsigned long long ok = __shfl_xor_sync(0xffffffffu, key, o);
                if (ok < key) key = ok;
            }
            if (lane == 0) wred[wid*8 + r] = key;
        }
        __syncthreads();
        if (tid < 8) {
            int u = g0 + tid;
            if (u < cnt) {
                unsigned long long k = wred[tid];
                if (wred[8  + tid] < k) k = wred[8  + tid];
                if (wred[16 + tid] < k) k = wred[16 + tid];
                if (wred[24 + tid] < k) k = wred[24 + tid];
                int l = g_rlist[n*LPER + u];
                atomicMin(&g_fixkey[n*LPER + l], k);
            }
        }
        __syncthreads();
    }
}

// ---------------- unpack rescan indices ----------------
__global__ void unpack_kernel() {
    const int n = blockIdx.x;
    const int cnt = g_rcnt[n];
    for (int p = threadIdx.x; p < cnt; p += blockDim.x) {
        int l = g_rlist[n*LPER + p];
        int id = n*LPER + l;
        g_indices[id] = (int)(unsigned)(g_fixkey[id] & 0xFFFFFFFFull);
    }
}

// ---------------- gather + z_q + loss partials + indices out (float4) ----------------
__global__ void __launch_bounds__(256)
gather_kernel(const float* __restrict__ x, const float* __restrict__ emb,
              float* __restrict__ out, float* __restrict__ out_idx, int write_extras) {
    __shared__ int   midx[64];
    __shared__ float rows[64*129];
    __shared__ float red[256];
    const int n = blockIdx.x & 7, b = blockIdx.x >> 3, tid = threadIdx.x;

    if (tid < 64) {
        int m = g_indices[n*LPER + b*HLAT + tid];
        midx[tid] = m;
        if (write_extras) out_idx[b*(NCB*HLAT) + n*HLAT + tid] = (float)m;
    }
    __syncthreads();
    for (int idx = tid; idx < 64*32; idx += 256) {
        int r = idx >> 5, dq = (idx & 31) * 4;
        float4 v = *(const float4*)&emb[((size_t)n*MEMB + midx[r])*DEMB + dq];
        float* dst = &rows[r*129 + dq];
        dst[0] = v.x; dst[1] = v.y; dst[2] = v.z; dst[3] = v.w;
    }
    __syncthreads();
    float s = 0.f;
    const size_t base = (size_t)b*65536 + (size_t)n*8192;
    for (int idx4 = tid; idx4 < 2048; idx4 += 256) {
        int d = idx4 >> 4, h4 = (idx4 & 15) * 4;
        float4 q;
        q.x = rows[(h4+0)*129 + d];
        q.y = rows[(h4+1)*129 + d];
        q.z = rows[(h4+2)*129 + d];
        q.w = rows[(h4+3)*129 + d];
        float4 xv = *(const float4*)&x[base + d*64 + h4];
        *(float4*)&out[base + d*64 + h4] = q;
        float dx = xv.x - q.x, dy = xv.y - q.y, dz = xv.z - q.z, dw = xv.w - q.w;
        s += dx*dx + dy*dy + dz*dz + dw*dw;
    }
    red[tid] = s;
    __syncthreads();
    for (int st = 128; st; st >>= 1) { if (tid < st) red[tid] += red[tid+st]; __syncthreads(); }
    if (tid == 0) g_part[blockIdx.x] = red[0];
}

// ---------------- entropy ----------------
__global__ void entropy_kernel() {
    __shared__ int   hist[MEMB];
    __shared__ float red[256];
    const int n = blockIdx.x, tid = threadIdx.x;
    for (int i = tid; i < MEMB; i += 256) hist[i] = 0;
    __syncthreads();
    for (int l = tid; l < LPER; l += 256) atomicAdd(&hist[g_indices[n*LPER + l]], 1);
    __syncthreads();
    float s = 0.f;
    for (int m = tid; m < MEMB; m += 256) {
        float p = (float)hist[m] * (1.f / (float)LPER);
        s += p * logf(p + 1e-10f);
    }
    red[tid] = s;
    __syncthreads();
    for (int st = 128; st; st >>= 1) { if (tid < st) red[tid] += red[tid+st]; __syncthreads(); }
    if (tid == 0) g_ent[n] = -red[0];
}

// ---------------- finalize ----------------
__global__ void finalize_kernel(float* __restrict__ out, int write_scalars) {
    __shared__ float red[256];
    const int tid = threadIdx.x;
    float s = 0.f;
    for (int i = tid; i < 2048; i += 256) s += g_part[i];
    red[tid] = s;
    __syncthreads();
    for (int st = 128; st; st >>= 1) { if (tid < st) red[tid] += red[tid+st]; __syncthreads(); }
    if (tid == 0 && write_scalars) {
        float loss = 0.25f * red[0] / (float)ZQ_ELEMS;
        float ent = 0.f, perp = 0.f;
        #pragma unroll
        for (int n = 0; n < NCB; n++) { ent += g_ent[n]; perp += expf(g_ent[n]); }
        out[ZQ_ELEMS + 0] = loss;
        out[ZQ_ELEMS + 1] = ent * (1.f / NCB);
        out[ZQ_ELEMS + 2] = perp * (1.f / NCB);
    }
}

// ---------------- launch ----------------
extern "C" void kernel_launch(void* const* d_in, const int* in_sizes, int n_in,
                              void* d_out, int out_size) {
    const float* x   = (const float*)d_in[0];
    const float* emb = (const float*)d_in[1];
    if (n_in >= 2 && in_sizes[0] == NCB*MEMB*DEMB && in_sizes[1] == ZQ_ELEMS) {
        const float* t = x; x = emb; emb = t;
    }
    float* out = (float*)d_out;
    const int full = (out_size >= ZQ_ELEMS + 3 + IDX_ELEMS) ? 1 : 0;

    const int SMEM_ARG = 56320;
    cudaFuncSetAttribute(argmin_mma, cudaFuncAttributeMaxDynamicSharedMemorySize, SMEM_ARG);
    const int SMEM_PAIR = 128*132*4;
    cudaFuncSetAttribute(pairfix_kernel, cudaFuncAttributeMaxDynamicSharedMemorySize, SMEM_PAIR);
    const int SMEM_RES = (128*132 + 8*128 + 128 + 8) * 4 + 32 * 8;
    cudaFuncSetAttribute(rescan_kernel, cudaFuncAttributeMaxDynamicSharedMemorySize, SMEM_RES);

    esq_kernel<<<(NCB*MEMB + 255)/256, 256>>>(emb);
    xsq_kernel<<<BATCH*NCB, 256>>>(x);
    bprep_kernel<<<(NCB*MEMB*DEMB + 255)/256, 256>>>(emb);
    argmin_mma<<<NCB * (LPER/64), 256, SMEM_ARG>>>(x);
    packP_kernel<<<2048, 128>>>(x);
    packR_kernel<<<dim3(256, NCB), 128>>>(x);
    pairfix_kernel<<<296, 256, SMEM_PAIR>>>(emb);
    rescan_kernel<<<NCB*8*16, 128, SMEM_RES>>>(emb);
    unpack_kernel<<<NCB, 256>>>();
    gather_kernel<<<BATCH*NCB, 256>>>(x, emb, out, out + ZQ_ELEMS + 3, full);
    entropy_kernel<<<NCB, 256>>>();
    finalize_kernel<<<1, 256>>>(out, full);
}